// round 7
// baseline (speedup 1.0000x reference)
#include <cuda_runtime.h>
#include <math.h>

#define BB 32
#define VV 518
#define SS 2048
#define BV (BB*VV)
#define NTOK (BB*SS)
#define GROUPS 8
#define BPG 32                 // blocks per group (per batch)
#define ROUNDS (BB/GROUPS)     // 4
#define NBLK (GROUPS*BPG)      // 256 <= 296 resident at 2/SM: single wave
#define NT 512                 // threads per block
#define CPB (SS/BPG)           // 64 columns per block in phase 2
#define ROWBYTES (SS*4)

// Persistent scratch (allocations forbidden). All reset by k_init each launch.
__device__ double g_sum_nll;
__device__ double g_sum_mask;
__device__ unsigned int g_done;
__device__ unsigned int g_arrive[BB];
__device__ float  g_c[BV];
__device__ int    g_t64;

// ---------------------------------------------------------------------------
// Init: zero all counters/sums, detect target dtype (odd 32-bit words all
// zero over 64 entries <=> little-endian int64 with values < 518).
// ---------------------------------------------------------------------------
__global__ void k_init(const int* __restrict__ t32) {
    __shared__ int nz;
    if (threadIdx.x == 0) { nz = 0; g_sum_nll = 0.0; g_sum_mask = 0.0; g_done = 0u; }
    if (threadIdx.x < BB) g_arrive[threadIdx.x] = 0u;
    __syncthreads();
    if (threadIdx.x < 64 && t32[threadIdx.x * 2 + 1] != 0) atomicOr(&nz, 1);
    __syncthreads();
    if (threadIdx.x == 0) g_t64 = nz ? 0 : 1;
}

// per-element update for 2 columns
#define ACC2(X2, C, V)                                             \
    do {                                                           \
        sum0 += __expf((X2).x);  sum1 += __expf((X2).y);           \
        float _a = (X2).x - (C), _b = (X2).y - (C);                \
        if (_a > best0) { best0 = _a; bv0 = (V); }                 \
        if (_b > best1) { best1 = _b; bv1 = (V); }                 \
    } while (0)

// ---------------------------------------------------------------------------
// Fused, software-pipelined. Group g (32 blocks) owns batch b = 8r+g in
// round r. Program order per block:
//   P1(0); P1(1); { wait(0); P2(0); P1(2) } { wait(1); P2(1); P1(3) }
//   { wait(2); P2(2) } { wait(3); P2(3) }
// so the group barrier for round r is reached a full DRAM-phase after all
// peers signaled it -> near-zero wait, and P1 (DRAM) overlaps P2 (L2 hits,
// live footprint 2 rounds x 34MB = 68MB < 126MB L2).
// ---------------------------------------------------------------------------
__global__ __launch_bounds__(NT, 2)
void k_main(const float* __restrict__ X, const void* __restrict__ tptr,
            float* __restrict__ out) {
    __shared__ float sc[VV];
    __shared__ float s_sum[16][CPB];
    __shared__ float s_best[16][CPB];
    __shared__ int   s_bv[16][CPB];
    __shared__ double s_red[4];

    const int tid = threadIdx.x, w = tid >> 5, lane = tid & 31;
    const int g = blockIdx.x >> 5;       // group 0..7
    const int j = blockIdx.x & 31;       // block-in-group 0..31
    const int gw = j * 16 + w;           // 0..511 warp-in-group
    const int vlo = w * 32 + min(w, 6);  // phase-2 v-split: 6*33+10*32=518
    const int vhi = vlo + ((w < 6) ? 33 : 32);
    const int s0 = j * CPB;

    double acc_n = 0.0, acc_m = 0.0;

    // ---- Phase-1 body: row LSE for batch b (one warp/row, +2nd row for gw<6)
    auto phase1 = [&](int b) {
        const float* Xb = X + (size_t)b * VV * SS;
#pragma unroll
        for (int rep = 0; rep < 2; rep++) {
            int v = gw + rep * 512;
            if (v >= VV) break;
            const float4* rowp = (const float4*)(Xb + (size_t)v * SS);
            float a0 = 0.f, a1 = 0.f, a2 = 0.f, a3 = 0.f;
#pragma unroll 4
            for (int i = lane; i < SS/4; i += 32) {
                float4 x = rowp[i];
                a0 += __expf(x.x); a1 += __expf(x.y);
                a2 += __expf(x.z); a3 += __expf(x.w);
            }
            float a = (a0 + a1) + (a2 + a3);
#pragma unroll
            for (int o = 16; o; o >>= 1) a += __shfl_xor_sync(0xffffffffu, a, o);
            if (lane == 0) g_c[b * VV + v] = __logf(a);
        }
        __threadfence();
        __syncthreads();
        if (tid == 0) atomicAdd(&g_arrive[b], 1u);
    };

    // ---- Phase-2 body: column pass over this block's 64 s-positions
    auto phase2 = [&](int b) {
        const float* Xb = X + (size_t)b * VV * SS;

        if (tid == 0) {
            while (atomicAdd(&g_arrive[b], 0u) < BPG) __nanosleep(64);
        }
        __syncthreads();
        __threadfence();

        for (int i = tid; i < VV; i += NT) sc[i] = __ldcg(&g_c[b * VV + i]);
        __syncthreads();

        float sum0 = 0.f, sum1 = 0.f;
        float best0 = -INFINITY, best1 = -INFINITY;
        int bv0 = 0, bv1 = 0;

        const char* p = (const char*)Xb + (size_t)vlo * ROWBYTES
                      + (size_t)(s0 + lane * 2) * 4;
        int v = vlo;
        for (; v + 4 <= vhi; v += 4, p += 4 * ROWBYTES) {
            float2 x0 = *(const float2*)(p);
            float2 x1 = *(const float2*)(p + ROWBYTES);
            float2 x2 = *(const float2*)(p + 2 * ROWBYTES);
            float2 x3 = *(const float2*)(p + 3 * ROWBYTES);
            float c0 = sc[v], c1 = sc[v+1], c2 = sc[v+2], c3 = sc[v+3];
            ACC2(x0, c0, v);
            ACC2(x1, c1, v + 1);
            ACC2(x2, c2, v + 2);
            ACC2(x3, c3, v + 3);
        }
        for (; v < vhi; v++, p += ROWBYTES) {
            float2 x0 = *(const float2*)(p);
            float c0 = sc[v];
            ACC2(x0, c0, v);
        }

        {
            int j0 = lane * 2;
            s_sum[w][j0]  = sum0;  s_sum[w][j0+1]  = sum1;
            s_best[w][j0] = best0; s_best[w][j0+1] = best1;
            s_bv[w][j0]   = bv0;   s_bv[w][j0+1]   = bv1;
        }
        __syncthreads();

        if (tid < CPB) {
            const int jj = tid;
            int tgt;
            {
                int idx = b * SS + s0 + jj;
                if (g_t64) tgt = (int)((const long long*)tptr)[idx];
                else       tgt = ((const int*)tptr)[idx];
            }
            float txt = Xb[(size_t)tgt * SS + s0 + jj];

            float tsum = 0.f, tbest = -INFINITY;
            int tbv = 0;
#pragma unroll
            for (int c = 0; c < 16; c++) {        // ascending = first-max ties
                tsum += s_sum[c][jj];
                if (s_best[c][jj] > tbest) { tbest = s_best[c][jj]; tbv = s_bv[c][jj]; }
            }
            float nll = __logf(tsum) - txt;

            int pt = (tbv < 128) ? 0 : (tbv < 289) ? 1 : (tbv < 390) ? 2 : 3;
            int tt = (tgt < 128) ? 0 : (tgt < 289) ? 1 : (tgt < 390) ? 2 : 3;
            float mask;
            if (pt != tt) {
                mask = 1.0f;
            } else if (pt == 0) {
                mask = 0.5f;
            } else {
                float denom = (pt == 1) ? 160.f : (pt == 2) ? 100.f : 128.f;
                mask = 0.5f * fabsf((float)(tbv - tgt)) / denom;
            }

            double nd = (double)nll, md = (double)mask;
#pragma unroll
            for (int o = 16; o; o >>= 1) {
                nd += __shfl_xor_sync(0xffffffffu, nd, o);
                md += __shfl_xor_sync(0xffffffffu, md, o);
            }
            if (lane == 0) { s_red[w] = nd; s_red[2 + w] = md; }
        }
        __syncthreads();
        if (tid == 0) {
            acc_n += s_red[0] + s_red[1];
            acc_m += s_red[2] + s_red[3];
        }
        __syncthreads();   // smem reuse across rounds
    };

    // ---- software-pipelined schedule (1-round lookahead)
    phase1(0 * GROUPS + g);
    phase1(1 * GROUPS + g);
    phase2(0 * GROUPS + g);
    phase1(2 * GROUPS + g);
    phase2(1 * GROUPS + g);
    phase1(3 * GROUPS + g);
    phase2(2 * GROUPS + g);
    phase2(3 * GROUPS + g);

    if (tid == 0) {
        atomicAdd(&g_sum_nll, acc_n);
        atomicAdd(&g_sum_mask, acc_m);
        __threadfence();
        unsigned int done = atomicAdd(&g_done, 1u);
        if (done == NBLK - 1) {
            double nm = g_sum_nll / (double)NTOK;
            double mm = g_sum_mask / (double)NTOK;
            out[0] = (float)(nm * (1.0 + mm));
        }
    }
}

extern "C" void kernel_launch(void* const* d_in, const int* in_sizes, int n_in,
                              void* d_out, int out_size) {
    const float* X   = (const float*)d_in[0];
    const void*  tgt = d_in[1];
    float* out = (float*)d_out;

    k_init<<<1, 128>>>((const int*)tgt);
    k_main<<<NBLK, NT>>>(X, tgt, out);
}

// round 8
// speedup vs baseline: 1.2943x; 1.2943x over previous
#include <cuda_runtime.h>
#include <math.h>

#define BB 32
#define VV 518
#define SS 2048
#define BV (BB*VV)            // 16576 rows
#define NTOK (BB*SS)          // 65536
#define NW 16                 // warps per block
#define TS 128                // s-positions per block
#define NCH (SS/TS)           // 16 s-chunks per batch
#define NBLK (BB*NCH)         // 512 blocks
#define ROWBYTES (SS*4)       // 8192

// Persistent scratch (allocations forbidden). g_sum_*, g_done zero between
// launches (reset by the finishing block of k2; statically zero first call).
__device__ double g_sum_nll  = 0.0;
__device__ double g_sum_mask = 0.0;
__device__ unsigned int g_done = 0;
__device__ float g_rowpart[BV * NCH];  // per (b,v): 16 s-chunk partials of sum_s exp
__device__ float g_colsum[NTOK];       // per (b,s): sum_v exp
__device__ int   g_t64;                // 1 if target buffer is int64

// ---------------------------------------------------------------------------
// k1: single exp per element, feeding BOTH reductions.
// Block (b, chunk): warp w owns v-rows [vlo,vhi), lane owns 4 s-cols (float4).
// Per row: 4 exps -> column accumulators (regs) + row partial (shfl-reduce,
// one float store per (row, chunk)). Column partials combined in smem.
// Block 0 additionally detects target dtype (odd 32-bit words all zero over
// 64 entries <=> little-endian int64 with values < 518).
// ---------------------------------------------------------------------------
__global__ __launch_bounds__(NW*32, 2)
void k1(const float* __restrict__ X, const int* __restrict__ t32) {
    __shared__ float s_col[NW][TS];

    const int tid = threadIdx.x, w = tid >> 5, lane = tid & 31;
    const int b = blockIdx.x >> 4;
    const int chunk = blockIdx.x & 15;
    const int s0 = chunk * TS;
    // v-split: warps 0..5 get 33 rows, 6..15 get 32 (6*33+10*32 = 518)
    const int vlo = w * 32 + min(w, 6);
    const int vhi = vlo + ((w < 6) ? 33 : 32);

    if (blockIdx.x == 0) {
        __shared__ int nz;
        if (tid == 0) nz = 0;
        __syncthreads();
        if (tid < 64 && t32[tid * 2 + 1] != 0) atomicOr(&nz, 1);
        __syncthreads();
        if (tid == 0) g_t64 = nz ? 0 : 1;
    }

    float c0 = 0.f, c1 = 0.f, c2 = 0.f, c3 = 0.f;
    const char* p = (const char*)(X + (size_t)b * VV * SS + s0)
                  + (size_t)lane * 16 + (size_t)vlo * ROWBYTES;
    float* rp_out = &g_rowpart[((size_t)b * VV + vlo) * NCH + chunk];

#pragma unroll 2
    for (int v = vlo; v < vhi; v++, p += ROWBYTES, rp_out += NCH) {
        float4 x = *(const float4*)p;
        float e0 = __expf(x.x), e1 = __expf(x.y);
        float e2 = __expf(x.z), e3 = __expf(x.w);
        c0 += e0; c1 += e1; c2 += e2; c3 += e3;
        float rp = (e0 + e1) + (e2 + e3);
#pragma unroll
        for (int o = 16; o; o >>= 1) rp += __shfl_xor_sync(0xffffffffu, rp, o);
        if (lane == 0) *rp_out = rp;
    }

    s_col[w][lane*4 + 0] = c0;
    s_col[w][lane*4 + 1] = c1;
    s_col[w][lane*4 + 2] = c2;
    s_col[w][lane*4 + 3] = c3;
    __syncthreads();

    if (tid < TS) {
        float t = 0.f;
#pragma unroll
        for (int c = 0; c < NW; c++) t += s_col[c][tid];   // fixed order
        g_colsum[b * SS + s0 + tid] = t;
    }
}

// ---------------------------------------------------------------------------
// k2: exp-free argmax pass (L2-fed re-read of X) + NLL from precomputed sums.
// Block (b, chunk): load negated c[v] = -log(sum of 16 rowparts) to smem,
// then per element: score = x + nc[v], compare-select argmax (first-max ties
// preserved: ascending v in-thread, ascending warp-chunk in combine).
// NLL = log(colsum) - x[target] (direct gather). Last block finalizes.
// ---------------------------------------------------------------------------
__global__ __launch_bounds__(NW*32, 2)
void k2(const float* __restrict__ X, const void* __restrict__ tptr,
        float* __restrict__ out) {
    __shared__ float nc[VV];
    __shared__ float s_best[NW][TS];
    __shared__ int   s_bv[NW][TS];
    __shared__ double s_red[8];

    const int tid = threadIdx.x, w = tid >> 5, lane = tid & 31;
    const int b = blockIdx.x >> 4;
    const int s0 = (blockIdx.x & 15) * TS;
    const int vlo = w * 32 + min(w, 6);
    const int vhi = vlo + ((w < 6) ? 33 : 32);

    // c[v]: sum 16 chunk partials (fixed pairwise order), negate log
    for (int v = tid; v < VV; v += NW*32) {
        const float4* q = (const float4*)&g_rowpart[((size_t)b * VV + v) * NCH];
        float4 a = q[0], bq = q[1], cq = q[2], d = q[3];
        float s01 = ((a.x + a.y) + (a.z + a.w)) + ((bq.x + bq.y) + (bq.z + bq.w));
        float s23 = ((cq.x + cq.y) + (cq.z + cq.w)) + ((d.x + d.y) + (d.z + d.w));
        nc[v] = -__logf(s01 + s23);
    }
    __syncthreads();

    float best0 = -INFINITY, best1 = -INFINITY, best2 = -INFINITY, best3 = -INFINITY;
    int bv0 = 0, bv1 = 0, bv2 = 0, bv3 = 0;

    const char* p = (const char*)(X + (size_t)b * VV * SS + s0)
                  + (size_t)lane * 16 + (size_t)vlo * ROWBYTES;
    int v = vlo;
    for (; v + 4 <= vhi; v += 4, p += 4*ROWBYTES) {
        float4 x0 = *(const float4*)(p);
        float4 x1 = *(const float4*)(p + ROWBYTES);
        float4 x2 = *(const float4*)(p + 2*ROWBYTES);
        float4 x3 = *(const float4*)(p + 3*ROWBYTES);
        float n0 = nc[v], n1 = nc[v+1], n2 = nc[v+2], n3 = nc[v+3];
#define SEL1(X4, NC, VI)                                             \
        {                                                            \
            float a_ = (X4).x + (NC), b_ = (X4).y + (NC);            \
            float c_ = (X4).z + (NC), d_ = (X4).w + (NC);            \
            if (a_ > best0) { best0 = a_; bv0 = (VI); }              \
            if (b_ > best1) { best1 = b_; bv1 = (VI); }              \
            if (c_ > best2) { best2 = c_; bv2 = (VI); }              \
            if (d_ > best3) { best3 = d_; bv3 = (VI); }              \
        }
        SEL1(x0, n0, v);
        SEL1(x1, n1, v+1);
        SEL1(x2, n2, v+2);
        SEL1(x3, n3, v+3);
    }
    for (; v < vhi; v++, p += ROWBYTES) {
        float4 x0 = *(const float4*)(p);
        float n0 = nc[v];
        SEL1(x0, n0, v);
    }
#undef SEL1

    {
        int j0 = lane * 4;
        s_best[w][j0]   = best0; s_bv[w][j0]   = bv0;
        s_best[w][j0+1] = best1; s_bv[w][j0+1] = bv1;
        s_best[w][j0+2] = best2; s_bv[w][j0+2] = bv2;
        s_best[w][j0+3] = best3; s_bv[w][j0+3] = bv3;
    }
    __syncthreads();

    double nll_d = 0.0, mask_d = 0.0;
    if (tid < TS) {
        const int j = tid;
        int tgt;
        {
            int idx = b * SS + s0 + j;
            if (g_t64) tgt = (int)((const long long*)tptr)[idx];
            else       tgt = ((const int*)tptr)[idx];
        }
        float txt = X[(size_t)b * VV * SS + (size_t)tgt * SS + s0 + j];

        float tbest = -INFINITY;
        int tbv = 0;
#pragma unroll
        for (int c = 0; c < NW; c++) {           // ascending = first-max ties
            if (s_best[c][j] > tbest) { tbest = s_best[c][j]; tbv = s_bv[c][j]; }
        }
        float nll = __logf(g_colsum[b * SS + s0 + j]) - txt;

        int pt = (tbv < 128) ? 0 : (tbv < 289) ? 1 : (tbv < 390) ? 2 : 3;
        int tt = (tgt < 128) ? 0 : (tgt < 289) ? 1 : (tgt < 390) ? 2 : 3;
        float mask;
        if (pt != tt) {
            mask = 1.0f;
        } else if (pt == 0) {
            mask = 0.5f;
        } else {
            float denom = (pt == 1) ? 160.f : (pt == 2) ? 100.f : 128.f;
            mask = 0.5f * fabsf((float)(tbv - tgt)) / denom;
        }
        nll_d  = (double)nll;
        mask_d = (double)mask;

#pragma unroll
        for (int o = 16; o; o >>= 1) {
            nll_d  += __shfl_xor_sync(0xffffffffu, nll_d, o);
            mask_d += __shfl_xor_sync(0xffffffffu, mask_d, o);
        }
        if (lane == 0) { s_red[w] = nll_d; s_red[4 + w] = mask_d; }
    }
    __syncthreads();
    if (tid == 0) {
        double n = s_red[0] + s_red[1] + s_red[2] + s_red[3];
        double m = s_red[4] + s_red[5] + s_red[6] + s_red[7];
        atomicAdd(&g_sum_nll, n);
        atomicAdd(&g_sum_mask, m);
        __threadfence();
        unsigned int done = atomicAdd(&g_done, 1u);
        if (done == NBLK - 1) {
            double nm = g_sum_nll / (double)NTOK;
            double mm = g_sum_mask / (double)NTOK;
            out[0] = (float)(nm * (1.0 + mm));
            g_sum_nll = 0.0;
            g_sum_mask = 0.0;
            g_done = 0u;
        }
    }
}

extern "C" void kernel_launch(void* const* d_in, const int* in_sizes, int n_in,
                              void* d_out, int out_size) {
    const float* X   = (const float*)d_in[0];
    const void*  tgt = d_in[1];
    float* out = (float*)d_out;

    k1<<<NBLK, NW*32>>>(X, (const int*)tgt);
    k2<<<NBLK, NW*32>>>(X, tgt, out);
}